// round 3
// baseline (speedup 1.0000x reference)
#include <cuda_runtime.h>
#include <cuda_bf16.h>
#include <math.h>

#define NN 50000
#define EE 800000
#define C0 32
#define C1 64
#define KP 25
#define FIN 160   // 32 + 64 + 64

// ---------------- scratch (static device allocations; no cudaMalloc) --------
__device__ __align__(16) float  g_Y[(size_t)NN * KP * 64];   // 320 MB
__device__ __align__(16) float  g_H1[(size_t)NN * 64];
__device__ __align__(16) float  g_H2[(size_t)NN * 64];
__device__ __align__(16) float  g_AGG[(size_t)NN * 64];
__device__ __align__(16) float  g_DEG[NN];
__device__ __align__(16) float4 g_B[EE];
__device__ int    g_K0[EE];
__device__ int    g_src[EE];
__device__ int    g_dst[EE];

// ---------------- prep: basis + knot index + edge endpoints ------------------
// edge_index is INT32 (jax canonicalizes int64->int32 without x64 enabled).
__global__ void prep_kernel(const int* __restrict__ ei,
                            const float* __restrict__ ea) {
    int e = blockIdx.x * blockDim.x + threadIdx.x;
    if (e >= EE) return;
    g_src[e] = ei[e];
    g_dst[e] = ei[EE + e];
    float v0 = ea[2 * e + 0] * 4.0f;
    float v1 = ea[2 * e + 1] * 4.0f;
    float b0f = floorf(v0), b1f = floorf(v1);
    float f0 = v0 - b0f, f1 = v1 - b1f;
    int i0 = min((int)b0f, 3);
    int i1 = min((int)b1f, 3);
    g_K0[e] = i0 + 5 * i1;
    g_B[e] = make_float4((1.f - f0) * (1.f - f1),
                         f0 * (1.f - f1),
                         (1.f - f0) * f1,
                         f0 * f1);
}

// ---------------- zero accumulators -----------------------------------------
__global__ void zero_kernel() {
    int i = blockIdx.x * blockDim.x + threadIdx.x;
    if (i < NN * 64) g_AGG[i] = 0.0f;
    if (i < NN)      g_DEG[i] = 0.0f;
}

// ---------------- Y = X @ W[k]  (per kernel-index GEMM, 64x64 tiles) --------
// grid: (ceil(N/64), 25), block: 256 threads, 4x4 micro-tile per thread.
template <int CIN>
__global__ void gemm_y_kernel(const float* __restrict__ X,
                              const float* __restrict__ W) {
    __shared__ __align__(16) float Xs[CIN][68];   // transposed: Xs[c][row]
    __shared__ __align__(16) float Ws[CIN][68];   // Ws[c][col]

    const int k  = blockIdx.y;
    const int n0 = blockIdx.x * 64;
    const float* Wk = W + (size_t)k * CIN * 64;
    const int tid = threadIdx.x;

    // load X tile (transposed into smem)
    for (int i = tid; i < CIN * 16; i += 256) {
        int lin = i * 4;
        int r = lin / CIN;
        int c = lin % CIN;
        float4 v = make_float4(0.f, 0.f, 0.f, 0.f);
        if (n0 + r < NN)
            v = __ldg((const float4*)(X + (size_t)(n0 + r) * CIN + c));
        Xs[c + 0][r] = v.x; Xs[c + 1][r] = v.y;
        Xs[c + 2][r] = v.z; Xs[c + 3][r] = v.w;
    }
    // load W tile
    for (int i = tid; i < CIN * 16; i += 256) {
        int lin = i * 4;
        int r = lin / 64;
        int c = lin % 64;
        float4 v = __ldg((const float4*)(Wk + lin));
        Ws[r][c + 0] = v.x; Ws[r][c + 1] = v.y;
        Ws[r][c + 2] = v.z; Ws[r][c + 3] = v.w;
    }
    __syncthreads();

    const int tx = tid & 15;   // col group
    const int ty = tid >> 4;   // row group
    float acc[4][4];
    #pragma unroll
    for (int i = 0; i < 4; i++)
        #pragma unroll
        for (int j = 0; j < 4; j++) acc[i][j] = 0.f;

    #pragma unroll
    for (int kk = 0; kk < CIN; ++kk) {
        float4 av = *(const float4*)&Xs[kk][ty * 4];
        float4 bv = *(const float4*)&Ws[kk][tx * 4];
        float a[4] = {av.x, av.y, av.z, av.w};
        float b[4] = {bv.x, bv.y, bv.z, bv.w};
        #pragma unroll
        for (int i = 0; i < 4; i++)
            #pragma unroll
            for (int j = 0; j < 4; j++)
                acc[i][j] = fmaf(a[i], b[j], acc[i][j]);
    }

    #pragma unroll
    for (int i = 0; i < 4; i++) {
        int n = n0 + ty * 4 + i;
        if (n < NN) {
            float4 o = make_float4(acc[i][0], acc[i][1], acc[i][2], acc[i][3]);
            *(float4*)(g_Y + (size_t)n * (KP * 64) + k * 64 + tx * 4) = o;
        }
    }
}

// ---------------- per-edge gather + basis combine + vector-RED scatter ------
// 16 lanes per edge; each lane owns 4 consecutive output channels (float4).
__global__ void edge_kernel() {
    int t = blockIdx.x * blockDim.x + threadIdx.x;
    int e = t >> 4;
    int lane = t & 15;
    if (e >= EE) return;

    int src = g_src[e];
    int dst = g_dst[e];
    int k0  = g_K0[e];
    float4 b = g_B[e];

    const float4* base = (const float4*)(g_Y + (size_t)src * (KP * 64) + (size_t)k0 * 64);
    float4 r0 = __ldg(base + lane);        // row k0
    float4 r1 = __ldg(base + 16 + lane);   // row k0+1
    float4 r2 = __ldg(base + 80 + lane);   // row k0+5
    float4 r3 = __ldg(base + 96 + lane);   // row k0+6

    float4 m;
    m.x = b.x * r0.x + b.y * r1.x + b.z * r2.x + b.w * r3.x;
    m.y = b.x * r0.y + b.y * r1.y + b.z * r2.y + b.w * r3.y;
    m.z = b.x * r0.z + b.y * r1.z + b.z * r2.z + b.w * r3.z;
    m.w = b.x * r0.w + b.y * r1.w + b.z * r2.w + b.w * r3.w;

    float* dptr = g_AGG + (size_t)dst * 64 + lane * 4;
    asm volatile("red.global.add.v4.f32 [%0], {%1, %2, %3, %4};"
                 :: "l"(dptr), "f"(m.x), "f"(m.y), "f"(m.z), "f"(m.w)
                 : "memory");
    if (lane == 0) {
        asm volatile("red.global.add.f32 [%0], %1;"
                     :: "l"(g_DEG + dst), "f"(1.0f) : "memory");
    }
}

// ---------------- finalize: mean + root GEMM + bias + relu ------------------
// block: 512 threads = 8 nodes x 64 outputs
template <int CIN>
__global__ void finalize_kernel(const float* __restrict__ X,
                                const float* __restrict__ root,
                                const float* __restrict__ bias,
                                float* __restrict__ H) {
    __shared__ __align__(16) float rs[CIN * 64];
    __shared__ __align__(16) float xs[8][CIN];
    const int tid = threadIdx.x;

    for (int i = tid; i < CIN * 16; i += 512)
        ((float4*)rs)[i] = __ldg(((const float4*)root) + i);

    const int n0 = blockIdx.x * 8;
    for (int i = tid; i < 8 * CIN / 4; i += 512) {
        int lin = i * 4;
        int r = lin / CIN, c = lin % CIN;
        int n = n0 + r;
        float4 v = make_float4(0.f, 0.f, 0.f, 0.f);
        if (n < NN) v = __ldg((const float4*)(X + (size_t)n * CIN + c));
        *(float4*)&xs[r][c] = v;
    }
    __syncthreads();

    const int ln = tid >> 6;
    const int o  = tid & 63;
    const int n  = n0 + ln;
    if (n >= NN) return;

    float acc = 0.f;
    #pragma unroll
    for (int i = 0; i < CIN; i++)
        acc = fmaf(xs[ln][i], rs[i * 64 + o], acc);

    float inv = 1.0f / fmaxf(g_DEG[n], 1.0f);
    float v = g_AGG[(size_t)n * 64 + o] * inv + acc + __ldg(bias + o);
    H[(size_t)n * 64 + o] = fmaxf(v, 0.0f);
}

// ---------------- final: concat(x,h1,h2) @ fw + fb (fused, no concat) ------
// block: 512 threads = 8 nodes x 64 outputs
__global__ void final_kernel(const float* __restrict__ X,
                             const float* __restrict__ fw,
                             const float* __restrict__ fb,
                             float* __restrict__ out) {
    __shared__ __align__(16) float ws[FIN * 64];   // 40 KB
    __shared__ __align__(16) float xs[8][FIN];
    const int tid = threadIdx.x;

    for (int i = tid; i < FIN * 16; i += 512)
        ((float4*)ws)[i] = __ldg(((const float4*)fw) + i);

    const int n0 = blockIdx.x * 8;
    for (int i = tid; i < 8 * FIN / 4; i += 512) {
        int lin = i * 4;
        int r = lin / FIN, c = lin % FIN;
        int n = n0 + r;
        float4 v = make_float4(0.f, 0.f, 0.f, 0.f);
        if (n < NN) {
            if (c < 32)      v = __ldg((const float4*)(X    + (size_t)n * 32 + c));
            else if (c < 96) v = __ldg((const float4*)(g_H1 + (size_t)n * 64 + (c - 32)));
            else             v = __ldg((const float4*)(g_H2 + (size_t)n * 64 + (c - 96)));
        }
        *(float4*)&xs[r][c] = v;
    }
    __syncthreads();

    const int ln = tid >> 6;
    const int o  = tid & 63;
    const int n  = n0 + ln;
    if (n >= NN) return;

    float acc = __ldg(fb + o);
    #pragma unroll
    for (int i = 0; i < FIN; i++)
        acc = fmaf(xs[ln][i], ws[i * 64 + o], acc);
    out[(size_t)n * 64 + o] = acc;
}

// ---------------- launch -----------------------------------------------------
extern "C" void kernel_launch(void* const* d_in, const int* in_sizes, int n_in,
                              void* d_out, int out_size) {
    const float* x     = (const float*)d_in[0];
    const int*   ei    = (const int*)d_in[1];     // int32! (jax x64 disabled)
    const float* ea    = (const float*)d_in[2];
    const float* w0    = (const float*)d_in[3];
    const float* root0 = (const float*)d_in[4];
    const float* b0    = (const float*)d_in[5];
    const float* w1    = (const float*)d_in[6];
    const float* root1 = (const float*)d_in[7];
    const float* b1    = (const float*)d_in[8];
    const float* fw    = (const float*)d_in[9];
    const float* fb    = (const float*)d_in[10];
    float*       out   = (float*)d_out;

    float *h1p, *h2p;
    cudaGetSymbolAddress((void**)&h1p, g_H1);
    cudaGetSymbolAddress((void**)&h2p, g_H2);

    // prep (basis/widx/src/dst) — shared by both layers
    prep_kernel<<<(EE + 255) / 256, 256>>>(ei, ea);

    const int zgrid = (NN * 64 + 255) / 256;
    dim3 ggrid((NN + 63) / 64, KP);
    const int egrid = (EE * 16 + 255) / 256;
    const int fgrid = (NN + 7) / 8;

    // ---- layer 0 (cin = 32) ----
    zero_kernel<<<zgrid, 256>>>();
    gemm_y_kernel<C0><<<ggrid, 256>>>(x, w0);
    edge_kernel<<<egrid, 256>>>();
    finalize_kernel<C0><<<fgrid, 512>>>(x, root0, b0, h1p);

    // ---- layer 1 (cin = 64) ----
    zero_kernel<<<zgrid, 256>>>();
    gemm_y_kernel<C1><<<ggrid, 256>>>(h1p, w1);
    edge_kernel<<<egrid, 256>>>();
    finalize_kernel<C1><<<fgrid, 512>>>(h1p, root1, b1, h2p);

    // ---- final fused concat-GEMM ----
    final_kernel<<<fgrid, 512>>>(x, fw, fb, out);
}

// round 4
// speedup vs baseline: 1.1425x; 1.1425x over previous
#include <cuda_runtime.h>
#include <cuda_bf16.h>
#include <math.h>
#include <stdint.h>

#define NN 50000
#define EE 800000
#define C0 32
#define C1 64
#define KP 25
#define FIN 160   // 32 + 64 + 64
#define YSTRIDE (KP * 64)   // 1600

// ---------------- scratch (static device allocations; no cudaMalloc) --------
__device__ __align__(16) float  g_Y[(size_t)NN * YSTRIDE];   // 320 MB
__device__ __align__(16) float  g_H1[(size_t)NN * 64];
__device__ __align__(16) float  g_H2[(size_t)NN * 64];
__device__ __align__(16) float  g_AGG[(size_t)NN * 64];
__device__ __align__(16) float  g_DEG[NN];                   // holds 1/max(deg,1) after recip
__device__ __align__(16) float4 g_B[EE];
__device__ int    g_K0[EE];
__device__ int    g_src[EE];
__device__ int    g_dst[EE];

// ---------------- init: zero AGG + DEG --------------------------------------
__global__ void init_kernel() {
    int i = blockIdx.x * blockDim.x + threadIdx.x;
    if (i < NN * 64) g_AGG[i] = 0.0f;
    if (i < NN)      g_DEG[i] = 0.0f;
}

// ---------------- prep: basis + knot index + endpoints + degree -------------
// edge_index is INT32 (jax canonicalizes int64->int32 without x64 enabled).
__global__ void prep_kernel(const int* __restrict__ ei,
                            const float* __restrict__ ea) {
    int e = blockIdx.x * blockDim.x + threadIdx.x;
    if (e >= EE) return;
    int dst = ei[EE + e];
    g_src[e] = ei[e];
    g_dst[e] = dst;
    atomicAdd(&g_DEG[dst], 1.0f);
    float v0 = ea[2 * e + 0] * 4.0f;
    float v1 = ea[2 * e + 1] * 4.0f;
    float b0f = floorf(v0), b1f = floorf(v1);
    float f0 = v0 - b0f, f1 = v1 - b1f;
    int i0 = min((int)b0f, 3);
    int i1 = min((int)b1f, 3);
    g_K0[e] = i0 + 5 * i1;
    g_B[e] = make_float4((1.f - f0) * (1.f - f1),
                         f0 * (1.f - f1),
                         (1.f - f0) * f1,
                         f0 * f1);
}

__global__ void recip_kernel() {
    int i = blockIdx.x * blockDim.x + threadIdx.x;
    if (i < NN) g_DEG[i] = 1.0f / fmaxf(g_DEG[i], 1.0f);
}

// ---------------- tf32 helpers ----------------------------------------------
__device__ __forceinline__ uint32_t f2tf32(float v) {
    uint32_t r;
    asm("cvt.rna.tf32.f32 %0, %1;" : "=r"(r) : "f"(v));
    return r;
}

__device__ __forceinline__ void mma_tf32(float c[4], const uint32_t a[4],
                                         const uint32_t b[2]) {
    asm volatile(
        "mma.sync.aligned.m16n8k8.row.col.f32.tf32.tf32.f32 "
        "{%0,%1,%2,%3}, {%4,%5,%6,%7}, {%8,%9}, {%0,%1,%2,%3};\n"
        : "+f"(c[0]), "+f"(c[1]), "+f"(c[2]), "+f"(c[3])
        : "r"(a[0]), "r"(a[1]), "r"(a[2]), "r"(a[3]),
          "r"(b[0]), "r"(b[1]));
}

// column interleave within each 8-group: {0,4,1,5,2,6,3,7} -> pos
__device__ __forceinline__ int kperm(int kk) {
    return (kk & ~7) + ((kk & 3) * 2) + ((kk >> 2) & 1);
}

// ---------------- Y = X @ Wcat  via tf32 tensor cores -----------------------
// grid: (ceil(N/128), 25), 256 threads = 8 warps (4 M x 2 N), BM=128, BN=64.
template <int CIN>
__global__ void __launch_bounds__(256)
gemm_y_tc(const float* __restrict__ X, const float* __restrict__ W) {
    constexpr int S = CIN + 8;          // word stride, ≡8 (mod 32): conflict-free
    extern __shared__ uint32_t sh[];
    uint32_t* Xs = sh;                  // [128][S]
    uint32_t* Bs = sh + 128 * S;        // [64][S]  (W slice transposed)

    const int k   = blockIdx.y;
    const int n0  = blockIdx.x * 128;
    const int tid = threadIdx.x;
    const float* Wk = W + (size_t)k * CIN * 64;

    // ---- load X tile [128, CIN] (tf32, column-interleaved) ----
    for (int i = tid; i < 128 * CIN / 4; i += 256) {
        int r  = i / (CIN / 4);
        int c4 = (i % (CIN / 4)) * 4;
        float4 v = make_float4(0.f, 0.f, 0.f, 0.f);
        if (n0 + r < NN)
            v = __ldg((const float4*)(X + (size_t)(n0 + r) * CIN + c4));
        Xs[r * S + kperm(c4 + 0)] = f2tf32(v.x);
        Xs[r * S + kperm(c4 + 1)] = f2tf32(v.y);
        Xs[r * S + kperm(c4 + 2)] = f2tf32(v.z);
        Xs[r * S + kperm(c4 + 3)] = f2tf32(v.w);
    }
    // ---- load W slice [CIN, 64] transposed -> Bs[col][kin] ----
    for (int i = tid; i < CIN * 16; i += 256) {
        int kin = i / 16;
        int c4  = (i % 16) * 4;
        float4 v = __ldg((const float4*)(Wk + kin * 64 + c4));
        int kp = kperm(kin);
        Bs[(c4 + 0) * S + kp] = f2tf32(v.x);
        Bs[(c4 + 1) * S + kp] = f2tf32(v.y);
        Bs[(c4 + 2) * S + kp] = f2tf32(v.z);
        Bs[(c4 + 3) * S + kp] = f2tf32(v.w);
    }
    __syncthreads();

    const int wid  = tid >> 5;
    const int lane = tid & 31;
    const int gid  = lane >> 2;
    const int tig  = lane & 3;
    const int rowB = (wid >> 1) * 32;   // warpM * 32
    const int colB = (wid & 1) * 32;    // warpN * 32

    float c[2][4][4];
    #pragma unroll
    for (int mt = 0; mt < 2; mt++)
        #pragma unroll
        for (int nt = 0; nt < 4; nt++)
            #pragma unroll
            for (int j = 0; j < 4; j++) c[mt][nt][j] = 0.f;

    #pragma unroll
    for (int ks = 0; ks < CIN / 8; ks++) {
        uint32_t a[2][4], b[4][2];
        #pragma unroll
        for (int mt = 0; mt < 2; mt++) {
            const uint32_t* p = &Xs[(rowB + mt * 16 + gid) * S + ks * 8 + 2 * tig];
            uint2 lo = *(const uint2*)p;
            uint2 hi = *(const uint2*)(p + 8 * S);
            a[mt][0] = lo.x; a[mt][1] = hi.x; a[mt][2] = lo.y; a[mt][3] = hi.y;
        }
        #pragma unroll
        for (int nt = 0; nt < 4; nt++) {
            const uint32_t* q = &Bs[(colB + nt * 8 + gid) * S + ks * 8 + 2 * tig];
            uint2 bb = *(const uint2*)q;
            b[nt][0] = bb.x; b[nt][1] = bb.y;
        }
        #pragma unroll
        for (int mt = 0; mt < 2; mt++)
            #pragma unroll
            for (int nt = 0; nt < 4; nt++)
                mma_tf32(c[mt][nt], a[mt], b[nt]);
    }

    // ---- store C fragments to g_Y ----
    #pragma unroll
    for (int mt = 0; mt < 2; mt++) {
        #pragma unroll
        for (int nt = 0; nt < 4; nt++) {
            int row = n0 + rowB + mt * 16 + gid;
            int col = k * 64 + colB + nt * 8 + 2 * tig;
            if (row < NN)
                *(float2*)(g_Y + (size_t)row * YSTRIDE + col) =
                    make_float2(c[mt][nt][0], c[mt][nt][1]);
            if (row + 8 < NN)
                *(float2*)(g_Y + (size_t)(row + 8) * YSTRIDE + col) =
                    make_float2(c[mt][nt][2], c[mt][nt][3]);
        }
    }
}

// ---------------- per-edge gather + basis combine + vector-RED scatter ------
__global__ void edge_kernel() {
    int t = blockIdx.x * blockDim.x + threadIdx.x;
    int e = t >> 4;
    int lane = t & 15;
    if (e >= EE) return;

    int src = g_src[e];
    int dst = g_dst[e];
    int k0  = g_K0[e];
    float4 b = g_B[e];

    const float4* base = (const float4*)(g_Y + (size_t)src * YSTRIDE + (size_t)k0 * 64);
    float4 r0 = __ldg(base + lane);        // row k0
    float4 r1 = __ldg(base + 16 + lane);   // row k0+1
    float4 r2 = __ldg(base + 80 + lane);   // row k0+5
    float4 r3 = __ldg(base + 96 + lane);   // row k0+6

    float4 m;
    m.x = b.x * r0.x + b.y * r1.x + b.z * r2.x + b.w * r3.x;
    m.y = b.x * r0.y + b.y * r1.y + b.z * r2.y + b.w * r3.y;
    m.z = b.x * r0.z + b.y * r1.z + b.z * r2.z + b.w * r3.z;
    m.w = b.x * r0.w + b.y * r1.w + b.z * r2.w + b.w * r3.w;

    float* dptr = g_AGG + (size_t)dst * 64 + lane * 4;
    asm volatile("red.global.add.v4.f32 [%0], {%1, %2, %3, %4};"
                 :: "l"(dptr), "f"(m.x), "f"(m.y), "f"(m.z), "f"(m.w)
                 : "memory");
}

// ---------------- finalize: mean + root GEMM + bias + relu + re-zero AGG ----
template <int CIN>
__global__ void finalize_kernel(const float* __restrict__ X,
                                const float* __restrict__ root,
                                const float* __restrict__ bias,
                                float* __restrict__ H) {
    __shared__ __align__(16) float rs[CIN * 64];
    __shared__ __align__(16) float xs[8][CIN];
    const int tid = threadIdx.x;

    for (int i = tid; i < CIN * 16; i += 512)
        ((float4*)rs)[i] = __ldg(((const float4*)root) + i);

    const int n0 = blockIdx.x * 8;
    for (int i = tid; i < 8 * CIN / 4; i += 512) {
        int lin = i * 4;
        int r = lin / CIN, c = lin % CIN;
        int n = n0 + r;
        float4 v = make_float4(0.f, 0.f, 0.f, 0.f);
        if (n < NN) v = __ldg((const float4*)(X + (size_t)n * CIN + c));
        *(float4*)&xs[r][c] = v;
    }
    __syncthreads();

    const int ln = tid >> 6;
    const int o  = tid & 63;
    const int n  = n0 + ln;
    if (n >= NN) return;

    float acc = 0.f;
    #pragma unroll
    for (int i = 0; i < CIN; i++)
        acc = fmaf(xs[ln][i], rs[i * 64 + o], acc);

    float inv = g_DEG[n];   // precomputed 1/max(deg,1)
    size_t ai = (size_t)n * 64 + o;
    float v = g_AGG[ai] * inv + acc + __ldg(bias + o);
    g_AGG[ai] = 0.0f;       // re-zero for next layer's edge pass
    H[ai] = fmaxf(v, 0.0f);
}

// ---------------- final: concat(x,h1,h2) @ fw + fb (fused, no concat) ------
__global__ void final_kernel(const float* __restrict__ X,
                             const float* __restrict__ fw,
                             const float* __restrict__ fb,
                             float* __restrict__ out) {
    __shared__ __align__(16) float ws[FIN * 64];   // 40 KB
    __shared__ __align__(16) float xs[8][FIN];
    const int tid = threadIdx.x;

    for (int i = tid; i < FIN * 16; i += 512)
        ((float4*)ws)[i] = __ldg(((const float4*)fw) + i);

    const int n0 = blockIdx.x * 8;
    for (int i = tid; i < 8 * FIN / 4; i += 512) {
        int lin = i * 4;
        int r = lin / FIN, c = lin % FIN;
        int n = n0 + r;
        float4 v = make_float4(0.f, 0.f, 0.f, 0.f);
        if (n < NN) {
            if (c < 32)      v = __ldg((const float4*)(X    + (size_t)n * 32 + c));
            else if (c < 96) v = __ldg((const float4*)(g_H1 + (size_t)n * 64 + (c - 32)));
            else             v = __ldg((const float4*)(g_H2 + (size_t)n * 64 + (c - 96)));
        }
        *(float4*)&xs[r][c] = v;
    }
    __syncthreads();

    const int ln = tid >> 6;
    const int o  = tid & 63;
    const int n  = n0 + ln;
    if (n >= NN) return;

    float acc = __ldg(fb + o);
    #pragma unroll
    for (int i = 0; i < FIN; i++)
        acc = fmaf(xs[ln][i], ws[i * 64 + o], acc);
    out[(size_t)n * 64 + o] = acc;
}

// ---------------- launch -----------------------------------------------------
extern "C" void kernel_launch(void* const* d_in, const int* in_sizes, int n_in,
                              void* d_out, int out_size) {
    const float* x     = (const float*)d_in[0];
    const int*   ei    = (const int*)d_in[1];     // int32 (jax x64 disabled)
    const float* ea    = (const float*)d_in[2];
    const float* w0    = (const float*)d_in[3];
    const float* root0 = (const float*)d_in[4];
    const float* b0    = (const float*)d_in[5];
    const float* w1    = (const float*)d_in[6];
    const float* root1 = (const float*)d_in[7];
    const float* b1    = (const float*)d_in[8];
    const float* fw    = (const float*)d_in[9];
    const float* fb    = (const float*)d_in[10];
    float*       out   = (float*)d_out;

    float *h1p, *h2p;
    cudaGetSymbolAddress((void**)&h1p, g_H1);
    cudaGetSymbolAddress((void**)&h2p, g_H2);

    const int smem0 = 192 * (C0 + 8) * 4;   // 30720 B
    const int smem1 = 192 * (C1 + 8) * 4;   // 55296 B
    cudaFuncSetAttribute(gemm_y_tc<C0>, cudaFuncAttributeMaxDynamicSharedMemorySize, smem0);
    cudaFuncSetAttribute(gemm_y_tc<C1>, cudaFuncAttributeMaxDynamicSharedMemorySize, smem1);

    const int zgrid = (NN * 64 + 255) / 256;
    dim3 ggrid((NN + 127) / 128, KP);
    const int egrid = (EE * 16 + 255) / 256;
    const int fgrid = (NN + 7) / 8;

    init_kernel<<<zgrid, 256>>>();
    prep_kernel<<<(EE + 255) / 256, 256>>>(ei, ea);
    recip_kernel<<<(NN + 255) / 256, 256>>>();

    // ---- layer 0 (cin = 32) ----
    gemm_y_tc<C0><<<ggrid, 256, smem0>>>(x, w0);
    edge_kernel<<<egrid, 256>>>();
    finalize_kernel<C0><<<fgrid, 512>>>(x, root0, b0, h1p);

    // ---- layer 1 (cin = 64) ----
    gemm_y_tc<C1><<<ggrid, 256, smem1>>>(h1p, w1);
    edge_kernel<<<egrid, 256>>>();
    finalize_kernel<C1><<<fgrid, 512>>>(h1p, root1, b1, h2p);

    // ---- final fused concat-GEMM ----
    final_kernel<<<fgrid, 512>>>(x, fw, fb, out);
}

// round 7
// speedup vs baseline: 1.7007x; 1.4886x over previous
#include <cuda_runtime.h>
#include <cuda_fp16.h>
#include <math.h>
#include <stdint.h>

#define NN 50000
#define EE 800000
#define C0 32
#define C1 64
#define KP 25
#define FIN 160
#define YSTRIDE (KP * 64)   // 1600

// ---------------- scratch -----------------------------------------------------
__device__ __align__(16) __half g_Yh[(size_t)NN * YSTRIDE];  // 160 MB fp16
__device__ __align__(16) float  g_H1[(size_t)NN * 64];
__device__ __align__(16) float  g_H2[(size_t)NN * 64];
__device__ __align__(16) float  g_AGG[(size_t)NN * 64];
__device__ __align__(16) float  g_DEG[NN];                   // 1/max(deg,1) after recip
__device__ __align__(16) float4 g_B[EE];
__device__ int    g_K0[EE];
__device__ int    g_src[EE];
__device__ int    g_dst[EE];

// ---------------- init / prep / recip ----------------------------------------
__global__ void init_kernel() {
    int i = blockIdx.x * blockDim.x + threadIdx.x;
    if (i < NN * 64) g_AGG[i] = 0.0f;
    if (i < NN)      g_DEG[i] = 0.0f;
}

__global__ void prep_kernel(const int* __restrict__ ei,
                            const float* __restrict__ ea) {
    int e = blockIdx.x * blockDim.x + threadIdx.x;
    if (e >= EE) return;
    int dst = ei[EE + e];
    g_src[e] = ei[e];
    g_dst[e] = dst;
    atomicAdd(&g_DEG[dst], 1.0f);
    float v0 = ea[2 * e + 0] * 4.0f;
    float v1 = ea[2 * e + 1] * 4.0f;
    float b0f = floorf(v0), b1f = floorf(v1);
    float f0 = v0 - b0f, f1 = v1 - b1f;
    int i0 = min((int)b0f, 3);
    int i1 = min((int)b1f, 3);
    g_K0[e] = i0 + 5 * i1;
    g_B[e] = make_float4((1.f - f0) * (1.f - f1),
                         f0 * (1.f - f1),
                         (1.f - f0) * f1,
                         f0 * f1);
}

__global__ void recip_kernel() {
    int i = blockIdx.x * blockDim.x + threadIdx.x;
    if (i < NN) g_DEG[i] = 1.0f / fmaxf(g_DEG[i], 1.0f);
}

// ---------------- mma / ldmatrix helpers -------------------------------------
__device__ __forceinline__ uint32_t pack_h2(float a, float b) {
    uint32_t r;
    asm("cvt.rn.f16x2.f32 %0, %1, %2;" : "=r"(r) : "f"(b), "f"(a));
    return r;
}

__device__ __forceinline__ void mma_f16(float c[4], const uint32_t a[4],
                                        const uint32_t b[2]) {
    asm volatile(
        "mma.sync.aligned.m16n8k16.row.col.f32.f16.f16.f32 "
        "{%0,%1,%2,%3}, {%4,%5,%6,%7}, {%8,%9}, {%0,%1,%2,%3};\n"
        : "+f"(c[0]), "+f"(c[1]), "+f"(c[2]), "+f"(c[3])
        : "r"(a[0]), "r"(a[1]), "r"(a[2]), "r"(a[3]),
          "r"(b[0]), "r"(b[1]));
}

__device__ __forceinline__ void ldsm_x4(uint32_t r[4], uint32_t addr) {
    asm volatile("ldmatrix.sync.aligned.m8n8.x4.shared.b16 {%0,%1,%2,%3}, [%4];"
                 : "=r"(r[0]), "=r"(r[1]), "=r"(r[2]), "=r"(r[3]) : "r"(addr));
}

__device__ __forceinline__ void ldsm_x2t(uint32_t r[2], uint32_t addr) {
    asm volatile("ldmatrix.sync.aligned.m8n8.x2.trans.shared.b16 {%0,%1}, [%2];"
                 : "=r"(r[0]), "=r"(r[1]) : "r"(addr));
}

// ---------------- Y = X @ W[k] for all k, fp16 MMA, k-loop in block ----------
// grid: ceil(N/128); 256 threads = 8 warps (4M x 2N), warp tile 32x32.
// A fragments loaded ONCE (registers), per-k only B ldmatrix + MMA + store.
// NOTE: all ldmatrix row strides are multiples of 16 B (ldmatrix alignment rule).
template <int CIN>
__global__ void __launch_bounds__(256, 2)
gemm_y_h(const float* __restrict__ X, const float* __restrict__ W) {
    constexpr int SW = CIN / 2 + 4;   // Xs word stride: 20/36 words = 80/144 B (16B-mult)
    constexpr int WSW = 36;           // Ws word stride: 144 B = 16*9 (16B-mult, cf ldsm)
    constexpr int KS = CIN / 16;      // k16-steps
    constexpr int NJ = CIN / 16;      // float4 W-prefetch regs per thread
    __shared__ uint32_t Xs[128 * SW];
    __shared__ uint32_t Ws[CIN * WSW]; // [kin][64 halfs]

    const int tid  = threadIdx.x;
    const int lane = tid & 31;
    const int wid  = tid >> 5;
    const int gid  = lane >> 2;
    const int tig  = lane & 3;
    const int rowB = (wid >> 1) * 32;
    const int colB = (wid & 1) * 32;
    const int n0   = blockIdx.x * 128;

    // ---- X tile -> smem (fp16) ----
    for (int i = tid; i < 128 * (CIN / 4); i += 256) {
        int r  = i / (CIN / 4);
        int c4 = (i % (CIN / 4)) * 4;
        float4 v = make_float4(0.f, 0.f, 0.f, 0.f);
        if (n0 + r < NN)
            v = __ldg((const float4*)(X + (size_t)(n0 + r) * CIN + c4));
        *(uint2*)&Xs[r * SW + c4 / 2] =
            make_uint2(pack_h2(v.x, v.y), pack_h2(v.z, v.w));
    }
    // ---- prefetch W[0] ----
    float4 wreg[NJ];
    #pragma unroll
    for (int j = 0; j < NJ; j++)
        wreg[j] = __ldg((const float4*)W + tid + j * 256);
    __syncthreads();

    // ---- A fragments once ----
    uint32_t a[2][KS][4];
    #pragma unroll
    for (int mt = 0; mt < 2; mt++)
        #pragma unroll
        for (int ks = 0; ks < KS; ks++) {
            int m  = rowB + mt * 16 + (lane & 15);
            int kw = ks * 8 + (lane >> 4) * 4;
            uint32_t addr = (uint32_t)__cvta_generic_to_shared(&Xs[m * SW + kw]);
            ldsm_x4(a[mt][ks], addr);
        }

    // ---- k loop ----
    for (int k = 0; k < KP; k++) {
        // store W[k] slice to smem (packed fp16, [kin][n])
        #pragma unroll
        for (int j = 0; j < NJ; j++) {
            int lin = (tid + j * 256) * 4;
            int kin = lin / 64, nn = lin % 64;
            float4 v = wreg[j];
            *(uint2*)&Ws[kin * WSW + nn / 2] =
                make_uint2(pack_h2(v.x, v.y), pack_h2(v.z, v.w));
        }
        __syncthreads();
        if (k < KP - 1) {
            const float4* Wn = (const float4*)(W + (size_t)(k + 1) * CIN * 64);
            #pragma unroll
            for (int j = 0; j < NJ; j++)
                wreg[j] = __ldg(Wn + tid + j * 256);
        }

        float c[2][4][4];
        #pragma unroll
        for (int mt = 0; mt < 2; mt++)
            #pragma unroll
            for (int nt = 0; nt < 4; nt++)
                #pragma unroll
                for (int q = 0; q < 4; q++) c[mt][nt][q] = 0.f;

        #pragma unroll
        for (int nt = 0; nt < 4; nt++) {
            #pragma unroll
            for (int ks = 0; ks < KS; ks++) {
                uint32_t b[2];
                int kr = ks * 16 + (lane & 15);
                uint32_t addr = (uint32_t)__cvta_generic_to_shared(
                    &Ws[kr * WSW + (colB + nt * 8) / 2]);
                ldsm_x2t(b, addr);
                mma_f16(c[0][nt], a[0][ks], b);
                mma_f16(c[1][nt], a[1][ks], b);
            }
        }

        // store fp16 C
        #pragma unroll
        for (int mt = 0; mt < 2; mt++) {
            int row = n0 + rowB + mt * 16 + gid;
            #pragma unroll
            for (int nt = 0; nt < 4; nt++) {
                int col = k * 64 + colB + nt * 8 + 2 * tig;
                if (row < NN)
                    *(uint32_t*)&g_Yh[(size_t)row * YSTRIDE + col] =
                        pack_h2(c[mt][nt][0], c[mt][nt][1]);
                if (row + 8 < NN)
                    *(uint32_t*)&g_Yh[(size_t)(row + 8) * YSTRIDE + col] =
                        pack_h2(c[mt][nt][2], c[mt][nt][3]);
            }
        }
        __syncthreads();
    }
}

// ---------------- per-edge gather (fp16 Y) + combine + vector-RED scatter ----
__global__ void edge_kernel() {
    int t = blockIdx.x * blockDim.x + threadIdx.x;
    int e = t >> 4;
    int lane = t & 15;
    if (e >= EE) return;

    int src = g_src[e];
    int dst = g_dst[e];
    int k0  = g_K0[e];
    float4 b = g_B[e];

    const uint2* base = (const uint2*)(g_Yh + (size_t)src * YSTRIDE + k0 * 64);
    uint2 q0 = __ldg(base + lane);        // row k0
    uint2 q1 = __ldg(base + 16 + lane);   // row k0+1
    uint2 q2 = __ldg(base + 80 + lane);   // row k0+5
    uint2 q3 = __ldg(base + 96 + lane);   // row k0+6

    float2 a0 = __half22float2(*(__half2*)&q0.x), a1 = __half22float2(*(__half2*)&q0.y);
    float2 b0 = __half22float2(*(__half2*)&q1.x), b1 = __half22float2(*(__half2*)&q1.y);
    float2 c0 = __half22float2(*(__half2*)&q2.x), c1 = __half22float2(*(__half2*)&q2.y);
    float2 d0 = __half22float2(*(__half2*)&q3.x), d1 = __half22float2(*(__half2*)&q3.y);

    float4 m;
    m.x = b.x * a0.x + b.y * b0.x + b.z * c0.x + b.w * d0.x;
    m.y = b.x * a0.y + b.y * b0.y + b.z * c0.y + b.w * d0.y;
    m.z = b.x * a1.x + b.y * b1.x + b.z * c1.x + b.w * d1.x;
    m.w = b.x * a1.y + b.y * b1.y + b.z * c1.y + b.w * d1.y;

    float* dptr = g_AGG + (size_t)dst * 64 + lane * 4;
    asm volatile("red.global.add.v4.f32 [%0], {%1, %2, %3, %4};"
                 :: "l"(dptr), "f"(m.x), "f"(m.y), "f"(m.z), "f"(m.w)
                 : "memory");
}

// ---------------- finalize: mean + root GEMM + bias + relu + re-zero AGG ----
template <int CIN>
__global__ void finalize_kernel(const float* __restrict__ X,
                                const float* __restrict__ root,
                                const float* __restrict__ bias,
                                float* __restrict__ H) {
    __shared__ __align__(16) float rs[CIN * 64];
    __shared__ __align__(16) float xs[8][CIN];
    const int tid = threadIdx.x;

    for (int i = tid; i < CIN * 16; i += 512)
        ((float4*)rs)[i] = __ldg(((const float4*)root) + i);

    const int n0 = blockIdx.x * 8;
    for (int i = tid; i < 8 * CIN / 4; i += 512) {
        int lin = i * 4;
        int r = lin / CIN, c = lin % CIN;
        int n = n0 + r;
        float4 v = make_float4(0.f, 0.f, 0.f, 0.f);
        if (n < NN) v = __ldg((const float4*)(X + (size_t)n * CIN + c));
        *(float4*)&xs[r][c] = v;
    }
    __syncthreads();

    const int ln = tid >> 6;
    const int o  = tid & 63;
    const int n  = n0 + ln;
    if (n >= NN) return;

    float acc = 0.f;
    #pragma unroll
    for (int i = 0; i < CIN; i++)
        acc = fmaf(xs[ln][i], rs[i * 64 + o], acc);

    float inv = g_DEG[n];
    size_t ai = (size_t)n * 64 + o;
    float v = g_AGG[ai] * inv + acc + __ldg(bias + o);
    g_AGG[ai] = 0.0f;
    H[ai] = fmaxf(v, 0.0f);
}

// ---------------- final: concat(x,h1,h2) @ fw + fb --------------------------
__global__ void final_kernel(const float* __restrict__ X,
                             const float* __restrict__ fw,
                             const float* __restrict__ fb,
                             float* __restrict__ out) {
    __shared__ __align__(16) float ws[FIN * 64];
    __shared__ __align__(16) float xs[8][FIN];
    const int tid = threadIdx.x;

    for (int i = tid; i < FIN * 16; i += 512)
        ((float4*)ws)[i] = __ldg(((const float4*)fw) + i);

    const int n0 = blockIdx.x * 8;
    for (int i = tid; i < 8 * FIN / 4; i += 512) {
        int lin = i * 4;
        int r = lin / FIN, c = lin % FIN;
        int n = n0 + r;
        float4 v = make_float4(0.f, 0.f, 0.f, 0.f);
        if (n < NN) {
            if (c < 32)      v = __ldg((const float4*)(X    + (size_t)n * 32 + c));
            else if (c < 96) v = __ldg((const float4*)(g_H1 + (size_t)n * 64 + (c - 32)));
            else             v = __ldg((const float4*)(g_H2 + (size_t)n * 64 + (c - 96)));
        }
        *(float4*)&xs[r][c] = v;
    }
    __syncthreads();

    const int ln = tid >> 6;
    const int o  = tid & 63;
    const int n  = n0 + ln;
    if (n >= NN) return;

    float acc = __ldg(fb + o);
    #pragma unroll
    for (int i = 0; i < FIN; i++)
        acc = fmaf(xs[ln][i], ws[i * 64 + o], acc);
    out[(size_t)n * 64 + o] = acc;
}

// ---------------- launch -----------------------------------------------------
extern "C" void kernel_launch(void* const* d_in, const int* in_sizes, int n_in,
                              void* d_out, int out_size) {
    const float* x     = (const float*)d_in[0];
    const int*   ei    = (const int*)d_in[1];     // int32 (jax x64 disabled)
    const float* ea    = (const float*)d_in[2];
    const float* w0    = (const float*)d_in[3];
    const float* root0 = (const float*)d_in[4];
    const float* b0    = (const float*)d_in[5];
    const float* w1    = (const float*)d_in[6];
    const float* root1 = (const float*)d_in[7];
    const float* b1    = (const float*)d_in[8];
    const float* fw    = (const float*)d_in[9];
    const float* fb    = (const float*)d_in[10];
    float*       out   = (float*)d_out;

    float *h1p, *h2p;
    cudaGetSymbolAddress((void**)&h1p, g_H1);
    cudaGetSymbolAddress((void**)&h2p, g_H2);

    const int zgrid = (NN * 64 + 255) / 256;
    const int ggrid = (NN + 127) / 128;
    const int egrid = (EE * 16 + 255) / 256;
    const int fgrid = (NN + 7) / 8;

    init_kernel<<<zgrid, 256>>>();
    prep_kernel<<<(EE + 255) / 256, 256>>>(ei, ea);
    recip_kernel<<<(NN + 255) / 256, 256>>>();

    // ---- layer 0 (cin = 32) ----
    gemm_y_h<C0><<<ggrid, 256>>>(x, w0);
    edge_kernel<<<egrid, 256>>>();
    finalize_kernel<C0><<<fgrid, 512>>>(x, root0, b0, h1p);

    // ---- layer 1 (cin = 64) ----
    gemm_y_h<C1><<<ggrid, 256>>>(h1p, w1);
    edge_kernel<<<egrid, 256>>>();
    finalize_kernel<C1><<<fgrid, 512>>>(h1p, root1, b1, h2p);

    // ---- final fused concat-GEMM ----
    final_kernel<<<fgrid, 512>>>(x, fw, fb, out);
}